// round 2
// baseline (speedup 1.0000x reference)
#include <cuda_runtime.h>

#define F 128
#define NE 132      // F + NL
#define MT 128      // points per block
#define KC 32       // k chunk

__device__ __forceinline__ unsigned long long pk2(float a, float b) {
    unsigned long long r;
    asm("mov.b64 %0, {%1, %2};" : "=l"(r)
        : "r"(__float_as_uint(a)), "r"(__float_as_uint(b)));
    return r;
}
__device__ __forceinline__ void fma2(unsigned long long& d,
                                     unsigned long long a,
                                     unsigned long long b) {
    asm("fma.rn.f32x2 %0, %1, %2, %3;" : "=l"(d) : "l"(a), "l"(b), "l"(d));
}
__device__ __forceinline__ float2 up2(unsigned long long v) {
    unsigned lo, hi;
    asm("mov.b64 {%0, %1}, %2;" : "=r"(lo), "=r"(hi) : "l"(v));
    return make_float2(__uint_as_float(lo), __uint_as_float(hi));
}

__global__ __launch_bounds__(256, 2)
void ib_kernel(const float* __restrict__ x, const float* __restrict__ chi,
               const float* __restrict__ W, const float* __restrict__ b,
               float* __restrict__ a1, float* __restrict__ chiout, int n)
{
    __shared__ float ws[KC][F];        // W chunk, output cols 0..127
    __shared__ float ys[KC][MT + 4];   // y chunk (transposed), stride 132 (bank pad)
    __shared__ float wb_s[NE][4];      // W cols 128..131 (for b1)
    __shared__ float bias_s[NE];

    const int tid = threadIdx.x;
    const int tx = tid & 15;           // col group  (8 cols each)
    const int ty = tid >> 4;           // point group (8 points each)
    const int m0 = blockIdx.x * MT;
    const int YS = MT + 4;

    for (int e = tid; e < NE * 4; e += 256) {
        int k = e >> 2, j = e & 3;
        wb_s[k][j] = W[k * NE + F + j];
    }
    for (int e = tid; e < NE; e += 256) bias_s[e] = b[e];

    unsigned long long acc[8][4];
#pragma unroll
    for (int i = 0; i < 8; i++)
#pragma unroll
        for (int j = 0; j < 4; j++) acc[i][j] = 0ULL;
    float4 b1acc = make_float4(0.f, 0.f, 0.f, 0.f);

    for (int k0 = 0; k0 < NE; k0 += KC) {
        const int kc = (NE - k0 < KC) ? (NE - k0) : KC;
        __syncthreads();
        // ---- load W chunk (cols 0..127) ----
        for (int e = tid; e < kc * F; e += 256) {
            int kk = e >> 7, j = e & 127;
            ws[kk][j] = W[(k0 + kk) * NE + j];
        }
        // ---- load Y chunk (transposed) ----
        if (k0 < F) {
            for (int e = tid; e < MT * (KC / 4); e += 256) {
                int p = e >> 3, kq = e & 7;
                float4 v = make_float4(0.f, 0.f, 0.f, 0.f);
                if (m0 + p < n)
                    v = *(const float4*)&x[(size_t)(m0 + p) * F + k0 + kq * 4];
                float* yc = &ys[kq * 4][p];
                yc[0 * YS] = v.x; yc[1 * YS] = v.y;
                yc[2 * YS] = v.z; yc[3 * YS] = v.w;
            }
        } else {
            // final 4 k-rows are d_chi (segment sums of chi^2)
            if (tid < MT) {
                int p = tid;
                float s0 = 0.f, s1 = 0.f, s2 = 0.f, s3 = 0.f;
                if (m0 + p < n) {
                    const float4* cp = (const float4*)&chi[(size_t)(m0 + p) * 16];
                    float4 c0 = cp[0], c1 = cp[1], c2 = cp[2], c3 = cp[3];
                    s0 = c0.x * c0.x;
                    s1 = c0.y * c0.y + c0.z * c0.z + c0.w * c0.w;
                    s2 = c1.x * c1.x + c1.y * c1.y + c1.z * c1.z + c1.w * c1.w
                       + c2.x * c2.x;
                    s3 = c2.y * c2.y + c2.z * c2.z + c2.w * c2.w
                       + c3.x * c3.x + c3.y * c3.y + c3.z * c3.z + c3.w * c3.w;
                }
                ys[0][p] = s0; ys[1][p] = s1; ys[2][p] = s2; ys[3][p] = s3;
            }
        }
        __syncthreads();
        // ---- main microtile compute (8 points x 8 cols, packed f32x2) ----
        for (int kk = 0; kk < kc; kk++) {
            float4 ya = *(const float4*)&ys[kk][ty * 8];
            float4 yb = *(const float4*)&ys[kk][ty * 8 + 4];
            float4 wa = *(const float4*)&ws[kk][tx * 8];
            float4 wc = *(const float4*)&ws[kk][tx * 8 + 4];
            unsigned long long w01 = pk2(wa.x, wa.y), w23 = pk2(wa.z, wa.w);
            unsigned long long w45 = pk2(wc.x, wc.y), w67 = pk2(wc.z, wc.w);
            float yr[8] = {ya.x, ya.y, ya.z, ya.w, yb.x, yb.y, yb.z, yb.w};
#pragma unroll
            for (int i = 0; i < 8; i++) {
                unsigned long long yd = pk2(yr[i], yr[i]);
                fma2(acc[i][0], yd, w01);
                fma2(acc[i][1], yd, w23);
                fma2(acc[i][2], yd, w45);
                fma2(acc[i][3], yd, w67);
            }
        }
        // ---- b1 (output cols 128..131) accumulation, one point per thread ----
        if (tid < MT) {
#pragma unroll 4
            for (int kk = 0; kk < kc; kk++) {
                float yv = ys[kk][tid];
                float4 w4 = *(const float4*)&wb_s[k0 + kk][0];
                b1acc.x += yv * w4.x; b1acc.y += yv * w4.y;
                b1acc.z += yv * w4.z; b1acc.w += yv * w4.w;
            }
        }
    }

    // ---- write a1 ----
#pragma unroll
    for (int i = 0; i < 8; i++) {
        int p = m0 + ty * 8 + i;
        if (p < n) {
            float2 v0 = up2(acc[i][0]), v1 = up2(acc[i][1]);
            float2 v2 = up2(acc[i][2]), v3 = up2(acc[i][3]);
            int c = tx * 8;
            float4 o0, o1;
            o0.x = v0.x + bias_s[c + 0]; o0.y = v0.y + bias_s[c + 1];
            o0.z = v1.x + bias_s[c + 2]; o0.w = v1.y + bias_s[c + 3];
            o1.x = v2.x + bias_s[c + 4]; o1.y = v2.y + bias_s[c + 5];
            o1.z = v3.x + bias_s[c + 6]; o1.w = v3.y + bias_s[c + 7];
            *(float4*)&a1[(size_t)p * F + c]     = o0;
            *(float4*)&a1[(size_t)p * F + c + 4] = o1;
        }
    }
    // ---- write chi_out = b1[:, seg] * chi ----
    if (tid < MT) {
        int p = m0 + tid;
        if (p < n) {
            float b0  = b1acc.x + bias_s[F + 0];
            float b1v = b1acc.y + bias_s[F + 1];
            float b2  = b1acc.z + bias_s[F + 2];
            float b3  = b1acc.w + bias_s[F + 3];
            const float4* cp = (const float4*)&chi[(size_t)p * 16];
            float4 c0 = cp[0], c1 = cp[1], c2 = cp[2], c3 = cp[3];
            float4* op = (float4*)&chiout[(size_t)p * 16];
            float4 o;
            // seg: m0->l0 | m1..3->l1 | m4..8->l2 | m9..15->l3
            o.x = b0  * c0.x; o.y = b1v * c0.y; o.z = b1v * c0.z; o.w = b1v * c0.w;
            op[0] = o;
            o.x = b2 * c1.x; o.y = b2 * c1.y; o.z = b2 * c1.z; o.w = b2 * c1.w;
            op[1] = o;
            o.x = b2 * c2.x; o.y = b3 * c2.y; o.z = b3 * c2.z; o.w = b3 * c2.w;
            op[2] = o;
            o.x = b3 * c3.x; o.y = b3 * c3.y; o.z = b3 * c3.z; o.w = b3 * c3.w;
            op[3] = o;
        }
    }
}

extern "C" void kernel_launch(void* const* d_in, const int* in_sizes, int n_in,
                              void* d_out, int out_size) {
    const float* x   = (const float*)d_in[0];
    const float* chi = (const float*)d_in[1];
    // d_in[2] = point_mask (all ones, unused by the reference math)
    const float* W   = (const float*)d_in[3];
    const float* b   = (const float*)d_in[4];

    const int n = in_sizes[0] / F;
    float* out    = (float*)d_out;
    float* a1     = out;                       // n * 128
    float* chiout = out + (size_t)n * F;       // n * 16

    const int grid = (n + MT - 1) / MT;
    ib_kernel<<<grid, 256>>>(x, chi, W, b, a1, chiout, n);
}

// round 4
// speedup vs baseline: 1.3361x; 1.3361x over previous
#include <cuda_runtime.h>
#include <cstdint>

#define F_    128
#define NE_   132
#define MT_   256          // rows per CTA tile
#define NKP   68           // kpairs (K padded to 136)
#define NCOL  136          // padded output cols
#define PADB  136          // B col pad (words)
#define PADY  68           // y kpair pad (words)
#define PADS  136          // stage col pad (words)

// smem byte offsets
#define OFF_YHI   0u                       // [256][68] u32 : 69632
#define OFF_YLO   69632u
#define OFF_BHI   139264u                  // [68][136] u32 : 36992
#define OFF_BLO   176256u
#define OFF_BIAS  213248u                  // 136 f32
#define SMEM_REQ  213824u
// stage overlays y region: [256][136] f32 = 139264 bytes

__device__ __forceinline__ void split2(float v0, float v1,
                                       uint32_t& hi, uint32_t& lo) {
    asm("cvt.rn.bf16x2.f32 %0, %1, %2;" : "=r"(hi) : "f"(v1), "f"(v0));
    float h0 = __uint_as_float((hi & 0xFFFFu) << 16);
    float h1 = __uint_as_float(hi & 0xFFFF0000u);
    asm("cvt.rn.bf16x2.f32 %0, %1, %2;" : "=r"(lo) : "f"(v1 - h1), "f"(v0 - h0));
}

__device__ __forceinline__ void mma16(float* c, const uint32_t* a,
                                      uint32_t b0, uint32_t b1) {
    asm volatile(
        "mma.sync.aligned.m16n8k16.row.col.f32.bf16.bf16.f32 "
        "{%0,%1,%2,%3}, {%4,%5,%6,%7}, {%8,%9}, {%0,%1,%2,%3};"
        : "+f"(c[0]), "+f"(c[1]), "+f"(c[2]), "+f"(c[3])
        : "r"(a[0]), "r"(a[1]), "r"(a[2]), "r"(a[3]), "r"(b0), "r"(b1));
}
__device__ __forceinline__ void mma8(float* c, uint32_t a0, uint32_t a1,
                                     uint32_t b0) {
    asm volatile(
        "mma.sync.aligned.m16n8k8.row.col.f32.bf16.bf16.f32 "
        "{%0,%1,%2,%3}, {%4,%5}, {%6}, {%0,%1,%2,%3};"
        : "+f"(c[0]), "+f"(c[1]), "+f"(c[2]), "+f"(c[3])
        : "r"(a0), "r"(a1), "r"(b0));
}

__global__ __launch_bounds__(256)
void ib_mma_kernel(const float* __restrict__ x, const float* __restrict__ chi,
                   const float* __restrict__ W, const float* __restrict__ b,
                   float* __restrict__ a1, float* __restrict__ chiout, int n)
{
    extern __shared__ char sm[];
    uint32_t* y_hi  = (uint32_t*)(sm + OFF_YHI);
    uint32_t* y_lo  = (uint32_t*)(sm + OFF_YLO);
    uint32_t* B_hi  = (uint32_t*)(sm + OFF_BHI);
    uint32_t* B_lo  = (uint32_t*)(sm + OFF_BLO);
    float*    bias  = (float*)(sm + OFF_BIAS);
    float*    stage = (float*)(sm + OFF_YHI);   // overlays y

    const int tid  = threadIdx.x;
    const int wid  = tid >> 5;
    const int lane = tid & 31;
    const int g    = lane >> 2;      // group id (rows / cols within frag)
    const int t4   = lane & 3;       // thread-in-group (kpair select)
    const int wrow = wid * 32;       // warp's 32-row band

    // ---- one-time: W split -> B_hi/B_lo, bias ----
    for (int e = tid; e < NKP * NCOL; e += 256) {
        int kp = e / NCOL, c = e - kp * NCOL;
        int k0 = 2 * kp, k1 = k0 + 1;
        float w0 = (k0 < NE_ && c < NE_) ? W[k0 * NE_ + c] : 0.f;
        float w1 = (k1 < NE_ && c < NE_) ? W[k1 * NE_ + c] : 0.f;
        uint32_t h, l;
        split2(w0, w1, h, l);
        B_hi[kp * PADB + c] = h;
        B_lo[kp * PADB + c] = l;
    }
    for (int e = tid; e < NCOL; e += 256) bias[e] = (e < NE_) ? b[e] : 0.f;

    const int ntiles = (n + MT_ - 1) / MT_;

    for (int t = blockIdx.x; t < ntiles; t += gridDim.x) {
        const int m0 = t * MT_;
        const int rows_valid = (n - m0 < MT_) ? (n - m0) : MT_;
        __syncthreads();   // prev epilogue done; y region free; B ready

        // ---- producer: x -> y_hi/y_lo (bf16x2 pairs, [row][kpair]) ----
        {
            const float* xb = x + (size_t)m0 * F_;
#pragma unroll 4
            for (int i = 0; i < 32; i++) {
                int e = tid + i * 256;            // (row, kq) row-major
                int row = e >> 5, kq = e & 31;
                float4 v = make_float4(0.f, 0.f, 0.f, 0.f);
                if (row < rows_valid) v = *(const float4*)(xb + (size_t)e * 4);
                uint32_t h0, l0, h1, l1;
                split2(v.x, v.y, h0, l0);
                split2(v.z, v.w, h1, l1);
                *(uint2*)&y_hi[row * PADY + 2 * kq] = make_uint2(h0, h1);
                *(uint2*)&y_lo[row * PADY + 2 * kq] = make_uint2(l0, l1);
            }
            // d_chi rows: kpairs 64..65, zeros 66..67
            int row = tid;
            float4 c0 = make_float4(0, 0, 0, 0), c1 = c0, c2 = c0, c3 = c0;
            if (row < rows_valid) {
                const float4* cp = (const float4*)&chi[(size_t)(m0 + row) * 16];
                c0 = cp[0]; c1 = cp[1]; c2 = cp[2]; c3 = cp[3];
            }
            float s0 = c0.x * c0.x;
            float s1 = c0.y * c0.y + c0.z * c0.z + c0.w * c0.w;
            float s2 = c1.x * c1.x + c1.y * c1.y + c1.z * c1.z + c1.w * c1.w
                     + c2.x * c2.x;
            float s3 = c2.y * c2.y + c2.z * c2.z + c2.w * c2.w
                     + c3.x * c3.x + c3.y * c3.y + c3.z * c3.z + c3.w * c3.w;
            uint32_t h0, l0, h1, l1;
            split2(s0, s1, h0, l0);
            split2(s2, s3, h1, l1);
            *(uint2*)&y_hi[row * PADY + 64] = make_uint2(h0, h1);
            *(uint2*)&y_lo[row * PADY + 64] = make_uint2(l0, l1);
            *(uint2*)&y_hi[row * PADY + 66] = make_uint2(0u, 0u);
            *(uint2*)&y_lo[row * PADY + 66] = make_uint2(0u, 0u);
        }
        __syncthreads();

        // ---- main: per-warp m32 x n136, K = 8 x k16 + 1 x k8 ----
        float acc[2][17][4];
#pragma unroll
        for (int mt = 0; mt < 2; mt++)
#pragma unroll
            for (int nt = 0; nt < 17; nt++) {
                int col = nt * 8 + t4 * 2;
                acc[mt][nt][0] = bias[col];
                acc[mt][nt][1] = bias[col + 1];
                acc[mt][nt][2] = bias[col];
                acc[mt][nt][3] = bias[col + 1];
            }

#pragma unroll 1
        for (int ks = 0; ks < 8; ks++) {
            const int kb = ks * 8;
            uint32_t ah[2][4], al[2][4];
#pragma unroll
            for (int mt = 0; mt < 2; mt++) {
                int r0 = (wrow + mt * 16 + g) * PADY;
                int r8 = r0 + 8 * PADY;
                ah[mt][0] = y_hi[r0 + kb + t4];
                ah[mt][1] = y_hi[r8 + kb + t4];
                ah[mt][2] = y_hi[r0 + kb + t4 + 4];
                ah[mt][3] = y_hi[r8 + kb + t4 + 4];
                al[mt][0] = y_lo[r0 + kb + t4];
                al[mt][1] = y_lo[r8 + kb + t4];
                al[mt][2] = y_lo[r0 + kb + t4 + 4];
                al[mt][3] = y_lo[r8 + kb + t4 + 4];
            }
#pragma unroll
            for (int nt = 0; nt < 17; nt++) {
                int c = nt * 8 + g;
                uint32_t bh0 = B_hi[(kb + t4) * PADB + c];
                uint32_t bh1 = B_hi[(kb + t4 + 4) * PADB + c];
                uint32_t bl0 = B_lo[(kb + t4) * PADB + c];
                uint32_t bl1 = B_lo[(kb + t4 + 4) * PADB + c];
                mma16(acc[0][nt], ah[0], bh0, bh1);
                mma16(acc[1][nt], ah[1], bh0, bh1);
                mma16(acc[0][nt], al[0], bh0, bh1);
                mma16(acc[1][nt], al[1], bh0, bh1);
                mma16(acc[0][nt], ah[0], bl0, bl1);
                mma16(acc[1][nt], ah[1], bl0, bl1);
            }
        }
        {   // tail k8: kpairs 64..67
            uint32_t ah[2][2], al[2][2];
#pragma unroll
            for (int mt = 0; mt < 2; mt++) {
                int r0 = (wrow + mt * 16 + g) * PADY;
                int r8 = r0 + 8 * PADY;
                ah[mt][0] = y_hi[r0 + 64 + t4];
                ah[mt][1] = y_hi[r8 + 64 + t4];
                al[mt][0] = y_lo[r0 + 64 + t4];
                al[mt][1] = y_lo[r8 + 64 + t4];
            }
#pragma unroll
            for (int nt = 0; nt < 17; nt++) {
                int c = nt * 8 + g;
                uint32_t bh = B_hi[(64 + t4) * PADB + c];
                uint32_t bl = B_lo[(64 + t4) * PADB + c];
                mma8(acc[0][nt], ah[0][0], ah[0][1], bh);
                mma8(acc[1][nt], ah[1][0], ah[1][1], bh);
                mma8(acc[0][nt], al[0][0], al[0][1], bh);
                mma8(acc[1][nt], al[1][0], al[1][1], bh);
                mma8(acc[0][nt], ah[0][0], ah[0][1], bl);
                mma8(acc[1][nt], ah[1][0], ah[1][1], bl);
            }
        }
        __syncthreads();   // all warps done reading y; stage may overwrite

        // ---- stage accumulators ----
#pragma unroll
        for (int mt = 0; mt < 2; mt++)
#pragma unroll
            for (int nt = 0; nt < 17; nt++) {
                int row0 = wrow + mt * 16 + g;
                int col = nt * 8 + t4 * 2;
                *(float2*)&stage[row0 * PADS + col] =
                    make_float2(acc[mt][nt][0], acc[mt][nt][1]);
                *(float2*)&stage[(row0 + 8) * PADS + col] =
                    make_float2(acc[mt][nt][2], acc[mt][nt][3]);
            }
        __syncthreads();

        // ---- a1 out (coalesced) ----
        {
            float* ab = a1 + (size_t)m0 * F_;
#pragma unroll 4
            for (int i = 0; i < 32; i++) {
                int e = tid + i * 256;
                int row = e >> 5, cq = e & 31;
                if (row < rows_valid) {
                    float4 v = *(const float4*)&stage[row * PADS + cq * 4];
                    *(float4*)(ab + (size_t)e * 4) = v;
                }
            }
        }
        // ---- chi_out ----
        {
            int row = tid;
            if (row < rows_valid) {
                float b0  = stage[row * PADS + 128];
                float b1v = stage[row * PADS + 129];
                float b2  = stage[row * PADS + 130];
                float b3  = stage[row * PADS + 131];
                const float4* cp = (const float4*)&chi[(size_t)(m0 + row) * 16];
                float4 c0 = cp[0], c1 = cp[1], c2 = cp[2], c3 = cp[3];
                float4* op = (float4*)&chiout[(size_t)(m0 + row) * 16];
                float4 o;
                o.x = b0  * c0.x; o.y = b1v * c0.y; o.z = b1v * c0.z; o.w = b1v * c0.w;
                op[0] = o;
                o.x = b2 * c1.x; o.y = b2 * c1.y; o.z = b2 * c1.z; o.w = b2 * c1.w;
                op[1] = o;
                o.x = b2 * c2.x; o.y = b3 * c2.y; o.z = b3 * c2.z; o.w = b3 * c2.w;
                op[2] = o;
                o.x = b3 * c3.x; o.y = b3 * c3.y; o.z = b3 * c3.z; o.w = b3 * c3.w;
                op[3] = o;
            }
        }
    }
}

extern "C" void kernel_launch(void* const* d_in, const int* in_sizes, int n_in,
                              void* d_out, int out_size) {
    const float* x   = (const float*)d_in[0];
    const float* chi = (const float*)d_in[1];
    // d_in[2] = point_mask (all ones; unused by the math)
    const float* W   = (const float*)d_in[3];
    const float* b   = (const float*)d_in[4];

    const int n = in_sizes[0] / F_;
    float* out    = (float*)d_out;
    float* a1     = out;
    float* chiout = out + (size_t)n * F_;

    cudaFuncSetAttribute(ib_mma_kernel,
                         cudaFuncAttributeMaxDynamicSharedMemorySize, SMEM_REQ);
    int ntiles = (n + MT_ - 1) / MT_;
    int grid = ntiles < 152 ? ntiles : 152;
    ib_mma_kernel<<<grid, 256, SMEM_REQ>>>(x, chi, W, b, a1, chiout, n);
}

// round 5
// speedup vs baseline: 3.1412x; 2.3511x over previous
#include <cuda_runtime.h>
#include <cstdint>

#define F_    128
#define NE_   132
#define MT_   128          // rows per tile
#define NKP   68           // kpairs (K padded to 136)
#define NCOL  136
#define PADB  136          // B row stride (words)
#define XS    132          // x stage row stride (words, 528B)
#define CS    20           // chi stage row stride (words, 80B)

// smem byte offsets
#define OFF_X0   0u                 // [128][132] f32 : 67584
#define OFF_X1   67584u
#define OFF_CHI0 135168u            // [128][20] f32 : 10240
#define OFF_CHI1 145408u
#define OFF_B    155648u            // [68][136] u32 (fp16x2) : 36992
#define OFF_BIAS 192640u            // 136 f32
#define SMEM_REQ 193184u

__device__ __forceinline__ uint32_t s2u(const void* p) {
    uint32_t a;
    asm("{ .reg .u64 t; cvta.to.shared.u64 t, %1; cvt.u32.u64 %0, t; }"
        : "=r"(a) : "l"(p));
    return a;
}
// pack two f32 -> f16x2 word: lo half = v0 (even k), hi half = v1 (odd k)
__device__ __forceinline__ uint32_t packh(float v0, float v1) {
    uint32_t r;
    asm("cvt.rn.f16x2.f32 %0, %1, %2;" : "=r"(r) : "f"(v1), "f"(v0));
    return r;
}
__device__ __forceinline__ void mma16(float* c, const uint32_t* a,
                                      uint32_t b0, uint32_t b1) {
    asm volatile(
        "mma.sync.aligned.m16n8k16.row.col.f32.f16.f16.f32 "
        "{%0,%1,%2,%3}, {%4,%5,%6,%7}, {%8,%9}, {%0,%1,%2,%3};"
        : "+f"(c[0]), "+f"(c[1]), "+f"(c[2]), "+f"(c[3])
        : "r"(a[0]), "r"(a[1]), "r"(a[2]), "r"(a[3]), "r"(b0), "r"(b1));
}
__device__ __forceinline__ void mma8(float* c, uint32_t a0, uint32_t a1,
                                     uint32_t b0) {
    asm volatile(
        "mma.sync.aligned.m16n8k8.row.col.f32.f16.f16.f32 "
        "{%0,%1,%2,%3}, {%4,%5}, {%6}, {%0,%1,%2,%3};"
        : "+f"(c[0]), "+f"(c[1]), "+f"(c[2]), "+f"(c[3])
        : "r"(a0), "r"(a1), "r"(b0));
}
__device__ __forceinline__ void cpa16(uint32_t dst, const void* src, int sz) {
    asm volatile("cp.async.cg.shared.global [%0], [%1], 16, %2;"
                 :: "r"(dst), "l"(src), "r"(sz) : "memory");
}

__device__ __forceinline__ void issue_tile(uint32_t xdst, uint32_t cdst,
                                           const float* x, const float* chi,
                                           int m0, int rv, int tid) {
#pragma unroll
    for (int i = 0; i < 16; i++) {
        int c = tid + i * 256;            // 4096 16B chunks of x tile
        int row = c >> 5, seg = c & 31;
        const char* src = (const char*)x + (size_t)(m0 + row) * 512 + seg * 16;
        int sz = 16;
        if (row >= rv) { src = (const char*)x; sz = 0; }
        cpa16(xdst + row * (XS * 4) + seg * 16, src, sz);
    }
#pragma unroll
    for (int i = 0; i < 2; i++) {
        int c = tid + i * 256;            // 512 chunks of chi tile
        int row = c >> 2, seg = c & 3;
        const char* src = (const char*)chi + (size_t)(m0 + row) * 64 + seg * 16;
        int sz = 16;
        if (row >= rv) { src = (const char*)chi; sz = 0; }
        cpa16(cdst + row * (CS * 4) + seg * 16, src, sz);
    }
    asm volatile("cp.async.commit_group;" ::: "memory");
}

__global__ __launch_bounds__(256)
void ib_mma_kernel(const float* __restrict__ x, const float* __restrict__ chi,
                   const float* __restrict__ W, const float* __restrict__ b,
                   float* __restrict__ a1, float* __restrict__ chiout, int n)
{
    extern __shared__ char sm[];
    const uint32_t smb = s2u(sm);
    float*    xs[2]  = {(float*)(sm + OFF_X0), (float*)(sm + OFF_X1)};
    float*    cs[2]  = {(float*)(sm + OFF_CHI0), (float*)(sm + OFF_CHI1)};
    const uint32_t xsu[2] = {smb + OFF_X0, smb + OFF_X1};
    const uint32_t csu[2] = {smb + OFF_CHI0, smb + OFF_CHI1};
    uint32_t* Bh   = (uint32_t*)(sm + OFF_B);
    float*    bias = (float*)(sm + OFF_BIAS);

    const int tid  = threadIdx.x;
    const int wid  = tid >> 5;
    const int lane = tid & 31;
    const int g    = lane >> 2;
    const int t4   = lane & 3;
    const int r0   = wid * 16 + g;     // warp's rows: r0, r0+8
    const int r1   = r0 + 8;

    const int ntiles = (n + MT_ - 1) / MT_;
    int t = blockIdx.x;

    // prologue: start tile 0 fetch immediately
    {
        int m0 = t * MT_;
        int rv = (n - m0 < MT_) ? (n - m0) : MT_;
        issue_tile(xsu[0], csu[0], x, chi, m0, rv, tid);
    }

    // one-time: W -> fp16x2 B table, bias
    for (int e = tid; e < NKP * NCOL; e += 256) {
        int kp = e / NCOL, c = e - kp * NCOL;
        int k0 = 2 * kp, k1 = k0 + 1;
        float w0 = (k0 < NE_ && c < NE_) ? W[k0 * NE_ + c] : 0.f;
        float w1 = (k1 < NE_ && c < NE_) ? W[k1 * NE_ + c] : 0.f;
        Bh[kp * PADB + c] = packh(w0, w1);
    }
    for (int e = tid; e < NCOL; e += 256) bias[e] = (e < NE_) ? b[e] : 0.f;

    for (int i = 0; t < ntiles; i++, t += gridDim.x) {
        const int buf = i & 1;
        const int m0 = t * MT_;
        const int rv = (n - m0 < MT_) ? (n - m0) : MT_;
        const int tn = t + gridDim.x;
        const bool has_next = (tn < ntiles);

        if (has_next) {
            int m0n = tn * MT_;
            int rvn = (n - m0n < MT_) ? (n - m0n) : MT_;
            issue_tile(xsu[buf ^ 1], csu[buf ^ 1], x, chi, m0n, rvn, tid);
            asm volatile("cp.async.wait_group 1;" ::: "memory");
        } else {
            asm volatile("cp.async.wait_group 0;" ::: "memory");
        }
        __syncthreads();   // tile t data visible to all

        const float* xsm = xs[buf];
        const float* csm = cs[buf];

        // ---- accumulators pre-loaded with bias ----
        float acc[17][4];
#pragma unroll
        for (int nt = 0; nt < 17; nt++) {
            int col = nt * 8 + t4 * 2;
            acc[nt][0] = bias[col];     acc[nt][1] = bias[col + 1];
            acc[nt][2] = bias[col];     acc[nt][3] = bias[col + 1];
        }

        // ---- main K: 8 x k16 over x features ----
#pragma unroll 1
        for (int ks = 0; ks < 8; ks++) {
            const int kb = 16 * ks + 2 * t4;
            float2 a00 = *(const float2*)&xsm[r0 * XS + kb];
            float2 a10 = *(const float2*)&xsm[r1 * XS + kb];
            float2 a01 = *(const float2*)&xsm[r0 * XS + kb + 8];
            float2 a11 = *(const float2*)&xsm[r1 * XS + kb + 8];
            uint32_t a[4];
            a[0] = packh(a00.x, a00.y);
            a[1] = packh(a10.x, a10.y);
            a[2] = packh(a01.x, a01.y);
            a[3] = packh(a11.x, a11.y);
            const uint32_t* B0 = &Bh[(8 * ks + t4) * PADB];
            const uint32_t* B1 = &Bh[(8 * ks + t4 + 4) * PADB];
#pragma unroll
            for (int nt = 0; nt < 17; nt++) {
                int c = nt * 8 + g;
                mma16(acc[nt], a, B0[c], B1[c]);
            }
        }

        // ---- tail k8: d_chi (cols 128..131 of K) ----
        {
            float s0a = 0.f, s1a = 0.f, s0b = 0.f, s1b = 0.f;
            if (t4 == 0) {
                float4 c0 = *(const float4*)&csm[r0 * CS];
                float4 d0 = *(const float4*)&csm[r1 * CS];
                s0a = c0.x * c0.x;
                s1a = c0.y * c0.y + c0.z * c0.z + c0.w * c0.w;
                s0b = d0.x * d0.x;
                s1b = d0.y * d0.y + d0.z * d0.z + d0.w * d0.w;
            } else if (t4 == 1) {
                float4 c1 = *(const float4*)&csm[r0 * CS + 4];
                float4 c2 = *(const float4*)&csm[r0 * CS + 8];
                float4 c3 = *(const float4*)&csm[r0 * CS + 12];
                s0a = c1.x * c1.x + c1.y * c1.y + c1.z * c1.z + c1.w * c1.w
                    + c2.x * c2.x;
                s1a = c2.y * c2.y + c2.z * c2.z + c2.w * c2.w
                    + c3.x * c3.x + c3.y * c3.y + c3.z * c3.z + c3.w * c3.w;
                float4 d1 = *(const float4*)&csm[r1 * CS + 4];
                float4 d2 = *(const float4*)&csm[r1 * CS + 8];
                float4 d3 = *(const float4*)&csm[r1 * CS + 12];
                s0b = d1.x * d1.x + d1.y * d1.y + d1.z * d1.z + d1.w * d1.w
                    + d2.x * d2.x;
                s1b = d2.y * d2.y + d2.z * d2.z + d2.w * d2.w
                    + d3.x * d3.x + d3.y * d3.y + d3.z * d3.z + d3.w * d3.w;
            }
            uint32_t ta0 = packh(s0a, s1a);
            uint32_t ta1 = packh(s0b, s1b);
            const uint32_t* Bt = &Bh[(64 + t4) * PADB];
#pragma unroll
            for (int nt = 0; nt < 17; nt++) {
                int c = nt * 8 + g;
                mma8(acc[nt], ta0, ta1, Bt[c]);
            }
        }

        // ---- epilogue: a1 direct from fragments (32B sectors per quad) ----
        {
            float* ab = a1 + (size_t)m0 * F_;
            const bool v0 = (r0 < rv), v1 = (r1 < rv);
#pragma unroll
            for (int nt = 0; nt < 16; nt++) {
                int col = nt * 8 + t4 * 2;
                if (v0) *(float2*)&ab[(size_t)r0 * F_ + col] =
                            make_float2(acc[nt][0], acc[nt][1]);
                if (v1) *(float2*)&ab[(size_t)r1 * F_ + col] =
                            make_float2(acc[nt][2], acc[nt][3]);
            }
            // chi_out: b-values live in acc[16] of lanes t4=0 (b0,b1), t4=1 (b2,b3)
            float c0 = acc[16][0], c1 = acc[16][1];
            float c2 = acc[16][2], c3 = acc[16][3];
            float o0 = __shfl_xor_sync(0xFFFFFFFFu, c0, 1);
            float o1 = __shfl_xor_sync(0xFFFFFFFFu, c1, 1);
            float o2 = __shfl_xor_sync(0xFFFFFFFFu, c2, 1);
            float o3 = __shfl_xor_sync(0xFFFFFFFFu, c3, 1);
            if (t4 == 0) {
                // rows r0, r1: cols 0..7 need (b0, b1, b2)
                float b0r[2] = {c0, c2}, b1r[2] = {c1, c3}, b2r[2] = {o0, o2};
                int rr[2] = {r0, r1};
#pragma unroll
                for (int h = 0; h < 2; h++) {
                    if (rr[h] < rv) {
                        const float* cr = &csm[rr[h] * CS];
                        float4 ca = *(const float4*)&cr[0];
                        float4 cb = *(const float4*)&cr[4];
                        float4 u, w;
                        u.x = b0r[h] * ca.x; u.y = b1r[h] * ca.y;
                        u.z = b1r[h] * ca.z; u.w = b1r[h] * ca.w;
                        w.x = b2r[h] * cb.x; w.y = b2r[h] * cb.y;
                        w.z = b2r[h] * cb.z; w.w = b2r[h] * cb.w;
                        float* op = &chiout[(size_t)(m0 + rr[h]) * 16];
                        *(float4*)&op[0] = u;
                        *(float4*)&op[4] = w;
                    }
                }
            } else if (t4 == 1) {
                // rows r0, r1: cols 8..15 need (b2, b3) = own (c0,c1)/(c2,c3)
                float b2r[2] = {c0, c2}, b3r[2] = {c1, c3};
                int rr[2] = {r0, r1};
#pragma unroll
                for (int h = 0; h < 2; h++) {
                    if (rr[h] < rv) {
                        const float* cr = &csm[rr[h] * CS];
                        float4 ca = *(const float4*)&cr[8];
                        float4 cb = *(const float4*)&cr[12];
                        float4 u, w;
                        u.x = b2r[h] * ca.x; u.y = b3r[h] * ca.y;
                        u.z = b3r[h] * ca.z; u.w = b3r[h] * ca.w;
                        w.x = b3r[h] * cb.x; w.y = b3r[h] * cb.y;
                        w.z = b3r[h] * cb.z; w.w = b3r[h] * cb.w;
                        float* op = &chiout[(size_t)(m0 + rr[h]) * 16];
                        *(float4*)&op[8]  = u;
                        *(float4*)&op[12] = w;
                    }
                }
            }
        }
        __syncthreads();   // all reads of buf done before it is refilled
    }
}

extern "C" void kernel_launch(void* const* d_in, const int* in_sizes, int n_in,
                              void* d_out, int out_size) {
    const float* x   = (const float*)d_in[0];
    const float* chi = (const float*)d_in[1];
    // d_in[2] = point_mask (all ones; unused by the math)
    const float* W   = (const float*)d_in[3];
    const float* b   = (const float*)d_in[4];

    const int n = in_sizes[0] / F_;
    float* out    = (float*)d_out;
    float* a1     = out;
    float* chiout = out + (size_t)n * F_;

    cudaFuncSetAttribute(ib_mma_kernel,
                         cudaFuncAttributeMaxDynamicSharedMemorySize, SMEM_REQ);
    int ntiles = (n + MT_ - 1) / MT_;
    int grid = ntiles < 152 ? ntiles : 152;
    ib_mma_kernel<<<grid, 256, SMEM_REQ>>>(x, chi, W, b, a1, chiout, n);
}